// round 13
// baseline (speedup 1.0000x reference)
#include <cuda_runtime.h>
#include <cuda_fp16.h>
#include <mma.h>
#include <cstdint>
#include <math.h>

using namespace nvcuda;

#define BC    2
#define LSEQ  2048
#define HIDD  1024
#define NH    16
#define HD    64
#define PFF   4096
#define MROWS (BC * LSEQ)
#define ATT_ELEMS ((size_t)BC * NH * LSEQ * LSEQ)

// ---------------- device scratch ----------------
__device__ __half g_qh  [MROWS * HIDD];
__device__ __half g_kh  [MROWS * HIDD];
__device__ __half g_vh  [MROWS * HIDD];
__device__ __half g_aoh [MROWS * HIDD];
__device__ __half g_hh  [MROWS * HIDD];
__device__ __half g_ffnh[(size_t)MROWS * PFF];
__device__ __half g_wth [16 * 1024 * 1024];
__device__ __half g_tgth[MROWS * HIDD];
__device__ __half g_ench[MROWS * HIDD];
__device__ __half g_sch [ATT_ELEMS];          // fp16 scores/probs
__device__ float  g_h   [MROWS * HIDD];       // fp32 residual carrier

// ---------------- helpers ----------------
__device__ __forceinline__ void cp16(uint32_t dst, const void* src) {
    asm volatile("cp.async.cg.shared.global [%0], [%1], 16;"
        :: "r"(dst), "l"(__cvta_generic_to_global(src)));
}
__device__ __forceinline__ uint32_t smem_u32(const void* p) {
    uint32_t a;
    asm("{ .reg .u64 t; cvta.to.shared.u64 t, %1; cvt.u32.u64 %0, t; }"
        : "=r"(a) : "l"(p));
    return a;
}

// ---------------------------------------------------------------------------
// fp16 wmma GEMM (fp32 accum): D[128 x NT] = A[128,K] @ B
// NTH threads (512 dense/scores, 256 PV).  BT=0: B row-major [K][N].
// BT=1: B K-major [N][K].
// MODE 1: half attn-layout out + bias      MODE 2: half relu + bias
// MODE 3: fp32 bias + residual row-major   MODE 5: half scores + mask
// MODE 6: half PV out, batched             MODE 7/8: fused QKV / KV
// ---------------------------------------------------------------------------
template<int MODE, int NT, int BT, int MINB, int STAGES, int NTH>
__global__ void __launch_bounds__(NTH, MINB)
tc_gemm(const __half* __restrict__ A, const __half* __restrict__ B,
        const float* __restrict__ bias0, const float* __restrict__ bias1,
        const float* __restrict__ bias2, const float* __restrict__ Rres,
        const int* __restrict__ mask,
        void* __restrict__ C0v, void* __restrict__ C1v, void* __restrict__ C2v,
        int K, int lda, int ldb, int ncols,
        long long aBatch, long long bBatch)
{
    constexpr int NW  = NTH / 32;
    constexpr int WY  = (NTH == 512) ? 4 : ((NT >= 128) ? 2 : 4);
    constexpr int WX  = NW / WY;
    constexpr int WTM = 128 / WY;
    constexpr int WTN = NT / WX;
    constexpr int FM  = WTM / 16;
    constexpr int FN  = WTN / 16;
    constexpr int AH   = 128 * 40;
    constexpr int BH   = BT ? NT * 40 : 32 * (NT + 8);
    constexpr int CHH  = AH + BH;
    constexpr int STG_R = NT + 4;
    constexpr int AIT  = 512 / NTH;               // A cp16 iterations
    constexpr int BIT  = 4 * NT / NTH;            // B cp16 iterations

    extern __shared__ float sm[];
    __half* smh = (__half*)sm;
    const uint32_t sb = smem_u32(sm);
    const int t = threadIdx.x, w = t >> 5;
    const int wy = w % WY, wx = w / WY;
    const int m0 = blockIdx.y * 128, n0 = blockIdx.x * NT;
    const int z  = blockIdx.z;

    const __half* Ab = A + (size_t)z * aBatch;
    const __half* Bb;
    if (MODE == 7 || MODE == 8)
        Bb = B + (size_t)(n0 >> 10) * 1048576 + (n0 & 1023);
    else if (BT == 1)
        Bb = B + (size_t)z * bBatch;
    else
        Bb = B + (size_t)z * bBatch + n0;

    wmma::fragment<wmma::accumulator, 16, 16, 16, float> cf[FM][FN];
#pragma unroll
    for (int i = 0; i < FM; i++)
#pragma unroll
        for (int j = 0; j < FN; j++) wmma::fill_fragment(cf[i][j], 0.0f);

    auto load_chunk = [&](int ci, int s) {
        const int k0 = ci * 32;
        const uint32_t abase = sb + (uint32_t)(s * CHH) * 2u;
#pragma unroll
        for (int j = 0; j < AIT; j++) {
            int id = j * NTH + t, row = id >> 2, c8 = (id & 3) * 8;
            cp16(abase + (uint32_t)(row * 40 + c8) * 2u,
                 Ab + (size_t)(m0 + row) * lda + k0 + c8);
        }
        const uint32_t bbase = abase + (uint32_t)AH * 2u;
        if (BT == 1) {
#pragma unroll
            for (int j = 0; j < BIT; j++) {
                int id = j * NTH + t, row = id >> 2, c8 = (id & 3) * 8;
                cp16(bbase + (uint32_t)(row * 40 + c8) * 2u,
                     Bb + (size_t)(n0 + row) * ldb + k0 + c8);
            }
        } else {
#pragma unroll
            for (int j = 0; j < BIT; j++) {
                int id = j * NTH + t, row = id / (NT / 8), c8 = (id % (NT / 8)) * 8;
                cp16(bbase + (uint32_t)(row * (NT + 8) + c8) * 2u,
                     Bb + (size_t)(k0 + row) * ldb + c8);
            }
        }
        asm volatile("cp.async.commit_group;");
    };

    const int nch = K / 32;
#pragma unroll
    for (int s = 0; s < STAGES - 1; s++)
        if (s < nch) load_chunk(s, s);

    for (int i = 0; i < nch; i++) {
        if (i + STAGES - 1 < nch) load_chunk(i + STAGES - 1, (i + STAGES - 1) % STAGES);
        else asm volatile("cp.async.commit_group;");
        if (STAGES == 4) asm volatile("cp.async.wait_group 3;");
        else             asm volatile("cp.async.wait_group 2;");
        __syncthreads();
        const __half* Ast = smh + (i % STAGES) * CHH;
        const __half* Bst = Ast + AH;
#pragma unroll
        for (int ks = 0; ks < 2; ks++) {
            wmma::fragment<wmma::matrix_a, 16, 16, 16, __half, wmma::row_major> af[FM];
#pragma unroll
            for (int fm = 0; fm < FM; fm++)
                wmma::load_matrix_sync(af[fm], Ast + (wy * WTM + fm * 16) * 40 + ks * 16, 40);
            if (BT == 1) {
#pragma unroll
                for (int fn = 0; fn < FN; fn++) {
                    wmma::fragment<wmma::matrix_b, 16, 16, 16, __half, wmma::col_major> bf;
                    wmma::load_matrix_sync(bf, Bst + (wx * WTN + fn * 16) * 40 + ks * 16, 40);
#pragma unroll
                    for (int fm = 0; fm < FM; fm++)
                        wmma::mma_sync(cf[fm][fn], af[fm], bf, cf[fm][fn]);
                }
            } else {
#pragma unroll
                for (int fn = 0; fn < FN; fn++) {
                    wmma::fragment<wmma::matrix_b, 16, 16, 16, __half, wmma::row_major> bf;
                    wmma::load_matrix_sync(bf, Bst + ks * 16 * (NT + 8) + wx * WTN + fn * 16, NT + 8);
#pragma unroll
                    for (int fm = 0; fm < FM; fm++)
                        wmma::mma_sync(cf[fm][fn], af[fm], bf, cf[fm][fn]);
                }
            }
        }
        __syncthreads();
    }
    __syncthreads();

    // ---- epilogue routing (block-uniform) ----
    int em = (MODE == 7 || MODE == 8) ? 1 : MODE;
    int nrel = n0;
    const float* bb = bias0;
    void* Ccv = C0v;
    if (MODE == 7) {
        int seg = n0 >> 10; nrel = n0 & 1023;
        Ccv = (seg == 0) ? C0v : (seg == 1) ? C1v : C2v;
        bb = (seg == 0) ? bias0 : (seg == 1) ? bias1 : bias2;
    }
    if (MODE == 8) {
        int seg = n0 >> 10; nrel = n0 & 1023;
        Ccv = seg ? C1v : C0v;
        bb = seg ? bias1 : bias0;
    }
    float*  Cf = (float*)Ccv;
    __half* Ch = (__half*)Ccv;

    float* stg = sm;
#pragma unroll
    for (int fm = 0; fm < FM; fm++)
#pragma unroll
        for (int fn = 0; fn < FN; fn++)
            wmma::store_matrix_sync(stg + (wy * WTM + fm * 16) * STG_R + wx * WTN + fn * 16,
                                    cf[fm][fn], STG_R, wmma::mem_row_major);
    __syncthreads();

    constexpr int QPR = NT / 4;
#pragma unroll
    for (int p = 0; p < (128 * QPR) / NTH; p++) {
        int idx = p * NTH + t;
        int rr = idx / QPR;
        int cq = (idx % QPR) * 4;
        float4 o = *(const float4*)&stg[rr * STG_R + cq];
        float vv[4] = {o.x, o.y, o.z, o.w};
#pragma unroll
        for (int c2 = 0; c2 < 4; c2++) {
            if (em == 1) vv[c2] += __ldg(&bb[nrel + cq + c2]);
            if (em == 2) vv[c2] = fmaxf(vv[c2] + __ldg(&bb[n0 + cq + c2]), 0.f);
            if (em == 3) vv[c2] += __ldg(&bb[n0 + cq + c2]);
            if (em == 5) {
                vv[c2] *= 0.125f;
                if (__ldg(&mask[(z >> 4) * LSEQ + n0 + cq + c2]) == 0) vv[c2] = -60000.f;
            }
        }
        if (em == 1 || em == 2 || em == 5 || em == 6) {
            __half2 h01 = __floats2half2_rn(vv[0], vv[1]);
            __half2 h23 = __floats2half2_rn(vv[2], vv[3]);
            uint2 u = { *(uint32_t*)&h01, *(uint32_t*)&h23 };
            if (em == 1) {
                int m = m0 + rr, b = m >> 11, l = m & 2047;
                int nr = nrel + cq, h = nr >> 6, d = nr & 63;
                *(uint2*)&Ch[(((size_t)(b * NH + h)) * LSEQ + l) * HD + d] = u;
            } else if (em == 6) {
                int b = z >> 4, h = z & 15;
                *(uint2*)&Ch[((size_t)(b * LSEQ + m0 + rr)) * HIDD + h * HD + n0 + cq] = u;
            } else if (em == 5) {
                *(uint2*)&Ch[(size_t)z * LSEQ * LSEQ + (size_t)(m0 + rr) * LSEQ + n0 + cq] = u;
            } else {
                *(uint2*)&Ch[(size_t)(m0 + rr) * ncols + n0 + cq] = u;
            }
        } else {
            o.x = vv[0]; o.y = vv[1]; o.z = vv[2]; o.w = vv[3];
            const float4 rv = *(const float4*)&Rres[(size_t)(m0 + rr) * ncols + n0 + cq];
            o.x += rv.x; o.y += rv.y; o.z += rv.z; o.w += rv.w;
            *(float4*)&Cf[(size_t)(m0 + rr) * ncols + n0 + cq] = o;
        }
    }
}

// ---------------------------------------------------------------------------
// fp32 -> fp16 convert: weights (16M floats), tgt, enc.
// ---------------------------------------------------------------------------
__global__ void __launch_bounds__(256)
cvt_k(const float4* s0, const float4* s1, const float4* s2, const float4* s3,
      const float4* s4, const float4* s5, const float4* s6, const float4* s7,
      const float4* f1, const float4* f2, const float4* tg, const float4* en,
      __half* wt, __half* tgth, __half* ench)
{
    long long idx4 = (long long)blockIdx.x * 256 + threadIdx.x;
    const float4* src; __half* dst;
    if (idx4 < 2097152) {
        int wsel = (int)(idx4 >> 18);
        long long o = idx4 & 262143;
        const float4* s = (wsel == 0) ? s0 : (wsel == 1) ? s1 : (wsel == 2) ? s2 :
                          (wsel == 3) ? s3 : (wsel == 4) ? s4 : (wsel == 5) ? s5 :
                          (wsel == 6) ? s6 : s7;
        src = s + o; dst = wt + idx4 * 4;
    } else if (idx4 < 3145728) { src = f1 + (idx4 - 2097152); dst = wt + idx4 * 4; }
    else if (idx4 < 4194304)   { src = f2 + (idx4 - 3145728); dst = wt + idx4 * 4; }
    else if (idx4 < 5242880)   { long long o = idx4 - 4194304; src = tg + o; dst = tgth + o * 4; }
    else                       { long long o = idx4 - 5242880; src = en + o; dst = ench + o * 4; }
    float4 v = *src;
    __half2 a = __floats2half2_rn(v.x, v.y);
    __half2 b = __floats2half2_rn(v.z, v.w);
    uint2 u = { *(uint32_t*)&a, *(uint32_t*)&b };
    *(uint2*)dst = u;
}

// ---------------------------------------------------------------------------
// Row softmax over LSEQ=2048, fp16 in, fp16 in-place; W32: fp32 probs out too.
// ---------------------------------------------------------------------------
template<int W32>
__global__ void __launch_bounds__(256)
softmax_hk(__half* __restrict__ Ph, float* __restrict__ S32)
{
    __half* ph = Ph + (size_t)blockIdx.x * LSEQ;
    const int t = threadIdx.x;
    const int base = t * 8;
    __shared__ float red[8];

    uint4 u = *(const uint4*)(ph + base);
    __half2 h0 = *(__half2*)&u.x, h1 = *(__half2*)&u.y;
    __half2 h2 = *(__half2*)&u.z, h3 = *(__half2*)&u.w;
    float2 f0 = __half22float2(h0), f1 = __half22float2(h1);
    float2 f2 = __half22float2(h2), f3 = __half22float2(h3);
    float v[8] = {f0.x, f0.y, f1.x, f1.y, f2.x, f2.y, f3.x, f3.y};

    float mx = -3.4e38f;
#pragma unroll
    for (int i = 0; i < 8; i++) mx = fmaxf(mx, v[i]);
#pragma unroll
    for (int o = 16; o; o >>= 1) mx = fmaxf(mx, __shfl_xor_sync(0xffffffffu, mx, o));
    if ((t & 31) == 0) red[t >> 5] = mx;
    __syncthreads();
    mx = red[0];
#pragma unroll
    for (int i = 1; i < 8; i++) mx = fmaxf(mx, red[i]);

    float s = 0.f;
#pragma unroll
    for (int i = 0; i < 8; i++) { v[i] = __expf(v[i] - mx); s += v[i]; }
#pragma unroll
    for (int o = 16; o; o >>= 1) s += __shfl_xor_sync(0xffffffffu, s, o);
    __syncthreads();
    if ((t & 31) == 0) red[t >> 5] = s;
    __syncthreads();
    s = 0.f;
#pragma unroll
    for (int i = 0; i < 8; i++) s += red[i];

    const float inv = 1.0f / s;
#pragma unroll
    for (int i = 0; i < 8; i++) v[i] *= inv;

    if (W32) {
        float* p32 = S32 + (size_t)blockIdx.x * LSEQ + base;
        float4 oa = {v[0], v[1], v[2], v[3]};
        float4 ob = {v[4], v[5], v[6], v[7]};
        *(float4*)p32 = oa;
        *(float4*)(p32 + 4) = ob;
    }
    __half2 o0 = __floats2half2_rn(v[0], v[1]);
    __half2 o1 = __floats2half2_rn(v[2], v[3]);
    __half2 o2 = __floats2half2_rn(v[4], v[5]);
    __half2 o3 = __floats2half2_rn(v[6], v[7]);
    uint4 ou = { *(uint32_t*)&o0, *(uint32_t*)&o1, *(uint32_t*)&o2, *(uint32_t*)&o3 };
    *(uint4*)(ph + base) = ou;
}

// ---------------------------------------------------------------------------
__global__ void __launch_bounds__(256)
ln_k(const float* __restrict__ X, const float* __restrict__ gam,
     const float* __restrict__ bet, float* __restrict__ Y, __half* __restrict__ Yh)
{
    const float* x = X + (size_t)blockIdx.x * HIDD;
    float*       y = Y + (size_t)blockIdx.x * HIDD;
    const int t = threadIdx.x;
    __shared__ float red[8];

    float v[4];
    float s = 0.f;
#pragma unroll
    for (int i = 0; i < 4; i++) { v[i] = x[t + 256 * i]; s += v[i]; }
#pragma unroll
    for (int o = 16; o; o >>= 1) s += __shfl_xor_sync(0xffffffffu, s, o);
    if ((t & 31) == 0) red[t >> 5] = s;
    __syncthreads();
    s = 0.f;
#pragma unroll
    for (int i = 0; i < 8; i++) s += red[i];
    const float mean = s * (1.0f / HIDD);

    float vs = 0.f;
#pragma unroll
    for (int i = 0; i < 4; i++) { float d = v[i] - mean; vs += d * d; }
#pragma unroll
    for (int o = 16; o; o >>= 1) vs += __shfl_xor_sync(0xffffffffu, vs, o);
    __syncthreads();
    if ((t & 31) == 0) red[t >> 5] = vs;
    __syncthreads();
    vs = 0.f;
#pragma unroll
    for (int i = 0; i < 8; i++) vs += red[i];
    const float inv = rsqrtf(vs * (1.0f / HIDD) + 1e-5f);

#pragma unroll
    for (int i = 0; i < 4; i++) {
        int c = t + 256 * i;
        float o = (v[i] - mean) * inv * gam[c] + bet[c];
        y[c] = o;
        if (Yh) Yh[(size_t)blockIdx.x * HIDD + c] = __float2half_rn(o);
    }
}

// ---------------------------------------------------------------------------
#define SMEM_D 133120   // max(4 stages pipeline 108544, fp32 staging 133120)
#define SMEM_S 133120
#define SMEM_P 44544

extern "C" void kernel_launch(void* const* d_in, const int* in_sizes, int n_in,
                              void* d_out, int out_size)
{
    const float* tgt    = (const float*)d_in[0];
    const float* enc    = (const float*)d_in[1];
    const int*   tmask  = (const int*)  d_in[2];
    const int*   smask  = (const int*)  d_in[3];
    const float* sa_wq  = (const float*)d_in[4],  *sa_bq = (const float*)d_in[5];
    const float* sa_wk  = (const float*)d_in[6],  *sa_bk = (const float*)d_in[7];
    const float* sa_wv  = (const float*)d_in[8],  *sa_bv = (const float*)d_in[9];
    const float* sa_wo  = (const float*)d_in[10], *sa_bo = (const float*)d_in[11];
    const float* ea_wq  = (const float*)d_in[12], *ea_bq = (const float*)d_in[13];
    const float* ea_wk  = (const float*)d_in[14], *ea_bk = (const float*)d_in[15];
    const float* ea_wv  = (const float*)d_in[16], *ea_bv = (const float*)d_in[17];
    const float* ea_wo  = (const float*)d_in[18], *ea_bo = (const float*)d_in[19];
    const float* ffn_w1 = (const float*)d_in[20], *ffn_b1 = (const float*)d_in[21];
    const float* ffn_w2 = (const float*)d_in[22], *ffn_b2 = (const float*)d_in[23];
    const float* ln1_g  = (const float*)d_in[24], *ln1_b = (const float*)d_in[25];
    const float* ln2_g  = (const float*)d_in[26], *ln2_b = (const float*)d_in[27];
    const float* ln3_g  = (const float*)d_in[28], *ln3_b = (const float*)d_in[29];

    float* out     = (float*)d_out;
    float* att_out = out + (size_t)BC * LSEQ * HIDD;

    __half *qh, *kh, *vh, *aoh, *hh, *ffnh, *wth, *tgth, *ench, *sch;
    float *h;
    cudaGetSymbolAddress((void**)&qh,   g_qh);
    cudaGetSymbolAddress((void**)&kh,   g_kh);
    cudaGetSymbolAddress((void**)&vh,   g_vh);
    cudaGetSymbolAddress((void**)&aoh,  g_aoh);
    cudaGetSymbolAddress((void**)&hh,   g_hh);
    cudaGetSymbolAddress((void**)&ffnh, g_ffnh);
    cudaGetSymbolAddress((void**)&wth,  g_wth);
    cudaGetSymbolAddress((void**)&tgth, g_tgth);
    cudaGetSymbolAddress((void**)&ench, g_ench);
    cudaGetSymbolAddress((void**)&sch,  g_sch);
    cudaGetSymbolAddress((void**)&h,    g_h);

    const size_t M1 = 1024 * 1024;

    cudaFuncSetAttribute(tc_gemm<7,256,0,1,4,512>, cudaFuncAttributeMaxDynamicSharedMemorySize, SMEM_D);
    cudaFuncSetAttribute(tc_gemm<8,256,0,1,4,512>, cudaFuncAttributeMaxDynamicSharedMemorySize, SMEM_D);
    cudaFuncSetAttribute(tc_gemm<1,256,0,1,4,512>, cudaFuncAttributeMaxDynamicSharedMemorySize, SMEM_D);
    cudaFuncSetAttribute(tc_gemm<2,256,0,1,4,512>, cudaFuncAttributeMaxDynamicSharedMemorySize, SMEM_D);
    cudaFuncSetAttribute(tc_gemm<3,256,0,1,4,512>, cudaFuncAttributeMaxDynamicSharedMemorySize, SMEM_D);
    cudaFuncSetAttribute(tc_gemm<5,256,1,1,3,512>, cudaFuncAttributeMaxDynamicSharedMemorySize, SMEM_S);
    cudaFuncSetAttribute(tc_gemm<6,64,0,2,3,256>,  cudaFuncAttributeMaxDynamicSharedMemorySize, SMEM_P);

    cvt_k<<<24576, 256>>>(
        (const float4*)sa_wq, (const float4*)sa_wk, (const float4*)sa_wv, (const float4*)sa_wo,
        (const float4*)ea_wq, (const float4*)ea_wk, (const float4*)ea_wv, (const float4*)ea_wo,
        (const float4*)ffn_w1, (const float4*)ffn_w2, (const float4*)tgt, (const float4*)enc,
        wth, tgth, ench);

    __half* w_saq = wth + 0 * M1; __half* w_sao = wth + 3 * M1;
    __half* w_eaq = wth + 4 * M1; __half* w_eak = wth + 5 * M1; __half* w_eao = wth + 7 * M1;
    __half* w_f1  = wth + 8 * M1; __half* w_f2  = wth + 12 * M1;

    const dim3 gqkv(12, 32);
    const dim3 gkv (8, 32);
    const dim3 gp  (4, 32);
    const dim3 gf1 (16, 32);
    const dim3 gsc (8, 16, BC * NH);
    const dim3 gpv (1, 16, BC * NH);
    const long long ABq = (long long)LSEQ * HD;
    const long long ABs = (long long)LSEQ * LSEQ;

    // ---- self-attention ----
    tc_gemm<7,256,0,1,4,512><<<gqkv, 512, SMEM_D>>>(tgth, w_saq, sa_bq, sa_bk, sa_bv, nullptr, nullptr,
                                                    qh, kh, vh, 1024, 1024, 1024, 1024, 0, 0);
    tc_gemm<5,256,1,1,3,512><<<gsc, 512, SMEM_S>>>(qh, kh, nullptr, nullptr, nullptr, nullptr, tmask,
                                                   sch, nullptr, nullptr, 64, 64, 64, 2048, ABq, ABq);
    softmax_hk<0><<<BC * NH * LSEQ, 256>>>(sch, nullptr);
    tc_gemm<6,64,0,2,3,256><<<gpv, 256, SMEM_P>>>(sch, vh, nullptr, nullptr, nullptr, nullptr, nullptr,
                                                  aoh, nullptr, nullptr, 2048, 2048, 64, 64, ABs, ABq);
    tc_gemm<3,256,0,1,4,512><<<gp, 512, SMEM_D>>>(aoh, w_sao, sa_bo, nullptr, nullptr, tgt, nullptr,
                                                  h, nullptr, nullptr, 1024, 1024, 1024, 1024, 0, 0);
    ln_k<<<MROWS, 256>>>(h, ln1_g, ln1_b, h, hh);

    // ---- cross-attention ----
    tc_gemm<1,256,0,1,4,512><<<gp, 512, SMEM_D>>>(hh, w_eaq, ea_bq, nullptr, nullptr, nullptr, nullptr,
                                                  qh, nullptr, nullptr, 1024, 1024, 1024, 1024, 0, 0);
    tc_gemm<8,256,0,1,4,512><<<gkv, 512, SMEM_D>>>(ench, w_eak, ea_bk, ea_bv, nullptr, nullptr, nullptr,
                                                   kh, vh, nullptr, 1024, 1024, 1024, 1024, 0, 0);
    tc_gemm<5,256,1,1,3,512><<<gsc, 512, SMEM_S>>>(qh, kh, nullptr, nullptr, nullptr, nullptr, smask,
                                                   sch, nullptr, nullptr, 64, 64, 64, 2048, ABq, ABq);
    softmax_hk<1><<<BC * NH * LSEQ, 256>>>(sch, att_out);
    tc_gemm<6,64,0,2,3,256><<<gpv, 256, SMEM_P>>>(sch, vh, nullptr, nullptr, nullptr, nullptr, nullptr,
                                                  aoh, nullptr, nullptr, 2048, 2048, 64, 64, ABs, ABq);
    tc_gemm<3,256,0,1,4,512><<<gp, 512, SMEM_D>>>(aoh, w_eao, ea_bo, nullptr, nullptr, h, nullptr,
                                                  h, nullptr, nullptr, 1024, 1024, 1024, 1024, 0, 0);
    ln_k<<<MROWS, 256>>>(h, ln2_g, ln2_b, h, hh);

    // ---- FFN ----
    tc_gemm<2,256,0,1,4,512><<<gf1, 512, SMEM_D>>>(hh, w_f1, ffn_b1, nullptr, nullptr, nullptr, nullptr,
                                                   ffnh, nullptr, nullptr, 1024, 1024, 4096, 4096, 0, 0);
    tc_gemm<3,256,0,1,4,512><<<gp, 512, SMEM_D>>>(ffnh, w_f2, ffn_b2, nullptr, nullptr, h, nullptr,
                                                  h, nullptr, nullptr, 4096, 4096, 1024, 1024, 0, 0);
    ln_k<<<MROWS, 256>>>(h, ln3_g, ln3_b, out, nullptr);
}

// round 14
// speedup vs baseline: 1.0645x; 1.0645x over previous
#include <cuda_runtime.h>
#include <cuda_fp16.h>
#include <mma.h>
#include <cstdint>
#include <math.h>

using namespace nvcuda;

#define BC    2
#define LSEQ  2048
#define HIDD  1024
#define NH    16
#define HD    64
#define PFF   4096
#define MROWS (BC * LSEQ)
#define ATT_ELEMS ((size_t)BC * NH * LSEQ * LSEQ)
#define NROWS_ATT (BC * NH * LSEQ)

// ---------------- device scratch ----------------
__device__ __half g_qh  [MROWS * HIDD];
__device__ __half g_kh  [MROWS * HIDD];
__device__ __half g_vh  [MROWS * HIDD];
__device__ __half g_aoh [MROWS * HIDD];
__device__ __half g_hh  [MROWS * HIDD];
__device__ __half g_ffnh[(size_t)MROWS * PFF];
__device__ __half g_wth [16 * 1024 * 1024];
__device__ __half g_tgth[MROWS * HIDD];
__device__ __half g_ench[MROWS * HIDD];
__device__ __half g_sch [ATT_ELEMS];          // fp16 scores/probs
__device__ float  g_h   [MROWS * HIDD];       // fp32 residual carrier
__device__ float  g_mr  [NROWS_ATT];          // row max
__device__ float  g_li  [NROWS_ATT];          // row 1/sum

// ---------------- helpers ----------------
__device__ __forceinline__ void cp16(uint32_t dst, const void* src) {
    asm volatile("cp.async.cg.shared.global [%0], [%1], 16;"
        :: "r"(dst), "l"(__cvta_generic_to_global(src)));
}
__device__ __forceinline__ uint32_t smem_u32(const void* p) {
    uint32_t a;
    asm("{ .reg .u64 t; cvta.to.shared.u64 t, %1; cvt.u32.u64 %0, t; }"
        : "=r"(a) : "l"(p));
    return a;
}

// ---------------------------------------------------------------------------
// fp16 wmma GEMM (fp32 accum): D[128 x NT] = A[128,K] @ B,  256 threads.
// BT=0: B row-major [K][N].  BT=1: B K-major [N][K].
// MODE 1: half attn-layout + bias      MODE 2: half relu + bias
// MODE 3: fp32 bias + residual         MODE 5: half scores + mask
// MODE 6: half PV out (probs in A)     MODE 7/8: fused QKV / KV
// MODE 9: PV from RAW scores: A transformed in smem via exp(s-m)*il
//         (bias0 = row-max array, bias1 = row-1/sum array)
// ---------------------------------------------------------------------------
template<int MODE, int NT, int BT, int MINB, int STAGES>
__global__ void __launch_bounds__(256, MINB)
tc_gemm(const __half* __restrict__ A, const __half* __restrict__ B,
        const float* __restrict__ bias0, const float* __restrict__ bias1,
        const float* __restrict__ bias2, const float* __restrict__ Rres,
        const int* __restrict__ mask,
        void* __restrict__ C0v, void* __restrict__ C1v, void* __restrict__ C2v,
        int K, int lda, int ldb, int ncols,
        long long aBatch, long long bBatch)
{
    constexpr int WY  = (NT >= 128) ? 2 : 4;
    constexpr int WX  = 8 / WY;
    constexpr int WTM = 128 / WY;
    constexpr int WTN = NT / WX;
    constexpr int FM  = WTM / 16;
    constexpr int FN  = WTN / 16;
    constexpr int AH   = 128 * 40;
    constexpr int BH   = BT ? NT * 40 : 32 * (NT + 8);
    constexpr int CHH  = AH + BH;
    constexpr int STG_R = NT + 4;

    extern __shared__ float sm[];
    __half* smh = (__half*)sm;
    const uint32_t sb = smem_u32(sm);
    const int t = threadIdx.x, w = t >> 5;
    const int wy = w % WY, wx = w / WY;
    const int m0 = blockIdx.y * 128, n0 = blockIdx.x * NT;
    const int z  = blockIdx.z;

    // MODE 9 row-stat smem (beyond pipeline area)
    float* s_m = (float*)(smh + STAGES * CHH);
    float* s_l = s_m + 128;
    if (MODE == 9 && t < 128) {
        s_m[t] = bias0[(size_t)z * LSEQ + m0 + t];
        s_l[t] = bias1[(size_t)z * LSEQ + m0 + t];
    }

    const __half* Ab = A + (size_t)z * aBatch;
    const __half* Bb;
    if (MODE == 7 || MODE == 8)
        Bb = B + (size_t)(n0 >> 10) * 1048576 + (n0 & 1023);
    else if (BT == 1)
        Bb = B + (size_t)z * bBatch;
    else
        Bb = B + (size_t)z * bBatch + n0;

    wmma::fragment<wmma::accumulator, 16, 16, 16, float> cf[FM][FN];
#pragma unroll
    for (int i = 0; i < FM; i++)
#pragma unroll
        for (int j = 0; j < FN; j++) wmma::fill_fragment(cf[i][j], 0.0f);

    auto load_chunk = [&](int ci, int s) {
        const int k0 = ci * 32;
        const uint32_t abase = sb + (uint32_t)(s * CHH) * 2u;
#pragma unroll
        for (int j = 0; j < 2; j++) {
            int id = j * 256 + t, row = id >> 2, c8 = (id & 3) * 8;
            cp16(abase + (uint32_t)(row * 40 + c8) * 2u,
                 Ab + (size_t)(m0 + row) * lda + k0 + c8);
        }
        const uint32_t bbase = abase + (uint32_t)AH * 2u;
        if (BT == 1) {
#pragma unroll
            for (int j = 0; j < NT / 64; j++) {
                int id = j * 256 + t, row = id >> 2, c8 = (id & 3) * 8;
                cp16(bbase + (uint32_t)(row * 40 + c8) * 2u,
                     Bb + (size_t)(n0 + row) * ldb + k0 + c8);
            }
        } else {
#pragma unroll
            for (int j = 0; j < NT / 64; j++) {
                int id = j * 256 + t, row = id / (NT / 8), c8 = (id % (NT / 8)) * 8;
                cp16(bbase + (uint32_t)(row * (NT + 8) + c8) * 2u,
                     Bb + (size_t)(k0 + row) * ldb + c8);
            }
        }
        asm volatile("cp.async.commit_group;");
    };

    const int nch = K / 32;
#pragma unroll
    for (int s = 0; s < STAGES - 1; s++)
        if (s < nch) load_chunk(s, s);

    for (int i = 0; i < nch; i++) {
        if (i + STAGES - 1 < nch) load_chunk(i + STAGES - 1, (i + STAGES - 1) % STAGES);
        else asm volatile("cp.async.commit_group;");
        if (STAGES == 4) asm volatile("cp.async.wait_group 3;");
        else             asm volatile("cp.async.wait_group 2;");
        __syncthreads();
        __half* Ast = smh + (i % STAGES) * CHH;
        const __half* Bst = Ast + AH;

        if (MODE == 9) {
            // transform raw scores -> normalized probs in smem
#pragma unroll
            for (int j = 0; j < 2; j++) {
                int id = j * 256 + t, row = id >> 2, c8 = (id & 3) * 8;
                float mrv = s_m[row], ilv = s_l[row];
                uint4* pp = (uint4*)(Ast + row * 40 + c8);
                uint4 u = *pp;
                __half2 h0 = *(__half2*)&u.x, h1 = *(__half2*)&u.y;
                __half2 h2 = *(__half2*)&u.z, h3 = *(__half2*)&u.w;
                float2 f0 = __half22float2(h0), f1 = __half22float2(h1);
                float2 f2 = __half22float2(h2), f3 = __half22float2(h3);
                f0.x = __expf(f0.x - mrv) * ilv; f0.y = __expf(f0.y - mrv) * ilv;
                f1.x = __expf(f1.x - mrv) * ilv; f1.y = __expf(f1.y - mrv) * ilv;
                f2.x = __expf(f2.x - mrv) * ilv; f2.y = __expf(f2.y - mrv) * ilv;
                f3.x = __expf(f3.x - mrv) * ilv; f3.y = __expf(f3.y - mrv) * ilv;
                h0 = __floats2half2_rn(f0.x, f0.y); h1 = __floats2half2_rn(f1.x, f1.y);
                h2 = __floats2half2_rn(f2.x, f2.y); h3 = __floats2half2_rn(f3.x, f3.y);
                u.x = *(uint32_t*)&h0; u.y = *(uint32_t*)&h1;
                u.z = *(uint32_t*)&h2; u.w = *(uint32_t*)&h3;
                *pp = u;
            }
            __syncthreads();
        }

#pragma unroll
        for (int ks = 0; ks < 2; ks++) {
            wmma::fragment<wmma::matrix_a, 16, 16, 16, __half, wmma::row_major> af[FM];
#pragma unroll
            for (int fm = 0; fm < FM; fm++)
                wmma::load_matrix_sync(af[fm], Ast + (wy * WTM + fm * 16) * 40 + ks * 16, 40);
            if (BT == 1) {
#pragma unroll
                for (int fn = 0; fn < FN; fn++) {
                    wmma::fragment<wmma::matrix_b, 16, 16, 16, __half, wmma::col_major> bf;
                    wmma::load_matrix_sync(bf, Bst + (wx * WTN + fn * 16) * 40 + ks * 16, 40);
#pragma unroll
                    for (int fm = 0; fm < FM; fm++)
                        wmma::mma_sync(cf[fm][fn], af[fm], bf, cf[fm][fn]);
                }
            } else {
#pragma unroll
                for (int fn = 0; fn < FN; fn++) {
                    wmma::fragment<wmma::matrix_b, 16, 16, 16, __half, wmma::row_major> bf;
                    wmma::load_matrix_sync(bf, Bst + ks * 16 * (NT + 8) + wx * WTN + fn * 16, NT + 8);
#pragma unroll
                    for (int fm = 0; fm < FM; fm++)
                        wmma::mma_sync(cf[fm][fn], af[fm], bf, cf[fm][fn]);
                }
            }
        }
        __syncthreads();
    }
    __syncthreads();

    // ---- epilogue routing (block-uniform) ----
    int em = (MODE == 7 || MODE == 8) ? 1 : ((MODE == 9) ? 6 : MODE);
    int nrel = n0;
    const float* bb = bias0;
    void* Ccv = C0v;
    if (MODE == 7) {
        int seg = n0 >> 10; nrel = n0 & 1023;
        Ccv = (seg == 0) ? C0v : (seg == 1) ? C1v : C2v;
        bb = (seg == 0) ? bias0 : (seg == 1) ? bias1 : bias2;
    }
    if (MODE == 8) {
        int seg = n0 >> 10; nrel = n0 & 1023;
        Ccv = seg ? C1v : C0v;
        bb = seg ? bias1 : bias0;
    }
    float*  Cf = (float*)Ccv;
    __half* Ch = (__half*)Ccv;

    float* stg = sm;
#pragma unroll
    for (int fm = 0; fm < FM; fm++)
#pragma unroll
        for (int fn = 0; fn < FN; fn++)
            wmma::store_matrix_sync(stg + (wy * WTM + fm * 16) * STG_R + wx * WTN + fn * 16,
                                    cf[fm][fn], STG_R, wmma::mem_row_major);
    __syncthreads();

    constexpr int QPR = NT / 4;
#pragma unroll
    for (int p = 0; p < (128 * QPR) / 256; p++) {
        int idx = p * 256 + t;
        int rr = idx / QPR;
        int cq = (idx % QPR) * 4;
        float4 o = *(const float4*)&stg[rr * STG_R + cq];
        float vv[4] = {o.x, o.y, o.z, o.w};
#pragma unroll
        for (int c2 = 0; c2 < 4; c2++) {
            if (em == 1) vv[c2] += __ldg(&bb[nrel + cq + c2]);
            if (em == 2) vv[c2] = fmaxf(vv[c2] + __ldg(&bb[n0 + cq + c2]), 0.f);
            if (em == 3) vv[c2] += __ldg(&bb[n0 + cq + c2]);
            if (em == 5) {
                vv[c2] *= 0.125f;
                if (__ldg(&mask[(z >> 4) * LSEQ + n0 + cq + c2]) == 0) vv[c2] = -60000.f;
            }
        }
        if (em == 1 || em == 2 || em == 5 || em == 6) {
            __half2 h01 = __floats2half2_rn(vv[0], vv[1]);
            __half2 h23 = __floats2half2_rn(vv[2], vv[3]);
            uint2 u = { *(uint32_t*)&h01, *(uint32_t*)&h23 };
            if (em == 1) {
                int m = m0 + rr, b = m >> 11, l = m & 2047;
                int nr = nrel + cq, h = nr >> 6, d = nr & 63;
                *(uint2*)&Ch[(((size_t)(b * NH + h)) * LSEQ + l) * HD + d] = u;
            } else if (em == 6) {
                int b = z >> 4, h = z & 15;
                *(uint2*)&Ch[((size_t)(b * LSEQ + m0 + rr)) * HIDD + h * HD + n0 + cq] = u;
            } else if (em == 5) {
                *(uint2*)&Ch[(size_t)z * LSEQ * LSEQ + (size_t)(m0 + rr) * LSEQ + n0 + cq] = u;
            } else {
                *(uint2*)&Ch[(size_t)(m0 + rr) * ncols + n0 + cq] = u;
            }
        } else {
            o.x = vv[0]; o.y = vv[1]; o.z = vv[2]; o.w = vv[3];
            const float4 rv = *(const float4*)&Rres[(size_t)(m0 + rr) * ncols + n0 + cq];
            o.x += rv.x; o.y += rv.y; o.z += rv.z; o.w += rv.w;
            *(float4*)&Cf[(size_t)(m0 + rr) * ncols + n0 + cq] = o;
        }
    }
}

// ---------------------------------------------------------------------------
// fp32 -> fp16 convert: weights, tgt, enc.
// ---------------------------------------------------------------------------
__global__ void __launch_bounds__(256)
cvt_k(const float4* s0, const float4* s1, const float4* s2, const float4* s3,
      const float4* s4, const float4* s5, const float4* s6, const float4* s7,
      const float4* f1, const float4* f2, const float4* tg, const float4* en,
      __half* wt, __half* tgth, __half* ench)
{
    long long idx4 = (long long)blockIdx.x * 256 + threadIdx.x;
    const float4* src; __half* dst;
    if (idx4 < 2097152) {
        int wsel = (int)(idx4 >> 18);
        long long o = idx4 & 262143;
        const float4* s = (wsel == 0) ? s0 : (wsel == 1) ? s1 : (wsel == 2) ? s2 :
                          (wsel == 3) ? s3 : (wsel == 4) ? s4 : (wsel == 5) ? s5 :
                          (wsel == 6) ? s6 : s7;
        src = s + o; dst = wt + idx4 * 4;
    } else if (idx4 < 3145728) { src = f1 + (idx4 - 2097152); dst = wt + idx4 * 4; }
    else if (idx4 < 4194304)   { src = f2 + (idx4 - 3145728); dst = wt + idx4 * 4; }
    else if (idx4 < 5242880)   { long long o = idx4 - 4194304; src = tg + o; dst = tgth + o * 4; }
    else                       { long long o = idx4 - 5242880; src = en + o; dst = ench + o * 4; }
    float4 v = *src;
    __half2 a = __floats2half2_rn(v.x, v.y);
    __half2 b = __floats2half2_rn(v.z, v.w);
    uint2 u = { *(uint32_t*)&a, *(uint32_t*)&b };
    *(uint2*)dst = u;
}

// ---------------------------------------------------------------------------
// Row stats: max + 1/sum of exp over 2048 fp16 scores (per row).
// ---------------------------------------------------------------------------
__global__ void __launch_bounds__(256)
stats_k(const __half* __restrict__ S, float* __restrict__ Mr, float* __restrict__ Li)
{
    const __half* p = S + (size_t)blockIdx.x * LSEQ;
    const int t = threadIdx.x;
    const int base = t * 8;
    __shared__ float red[8];

    uint4 u = *(const uint4*)(p + base);
    __half2 h0 = *(__half2*)&u.x, h1 = *(__half2*)&u.y;
    __half2 h2 = *(__half2*)&u.z, h3 = *(__half2*)&u.w;
    float2 f0 = __half22float2(h0), f1 = __half22float2(h1);
    float2 f2 = __half22float2(h2), f3 = __half22float2(h3);
    float v[8] = {f0.x, f0.y, f1.x, f1.y, f2.x, f2.y, f3.x, f3.y};

    float mx = -3.4e38f;
#pragma unroll
    for (int i = 0; i < 8; i++) mx = fmaxf(mx, v[i]);
#pragma unroll
    for (int o = 16; o; o >>= 1) mx = fmaxf(mx, __shfl_xor_sync(0xffffffffu, mx, o));
    if ((t & 31) == 0) red[t >> 5] = mx;
    __syncthreads();
    mx = red[0];
#pragma unroll
    for (int i = 1; i < 8; i++) mx = fmaxf(mx, red[i]);

    float s = 0.f;
#pragma unroll
    for (int i = 0; i < 8; i++) s += __expf(v[i] - mx);
#pragma unroll
    for (int o = 16; o; o >>= 1) s += __shfl_xor_sync(0xffffffffu, s, o);
    __syncthreads();
    if ((t & 31) == 0) red[t >> 5] = s;
    __syncthreads();
    if (t == 0) {
        s = 0.f;
#pragma unroll
        for (int i = 0; i < 8; i++) s += red[i];
        Mr[blockIdx.x] = mx;
        Li[blockIdx.x] = 1.0f / s;
    }
}

// ---------------------------------------------------------------------------
// Cross softmax: fp16 in, fp32 probs to S32 (output) + fp16 in-place.
// ---------------------------------------------------------------------------
__global__ void __launch_bounds__(256)
softmax_hk(__half* __restrict__ Ph, float* __restrict__ S32)
{
    __half* ph = Ph + (size_t)blockIdx.x * LSEQ;
    const int t = threadIdx.x;
    const int base = t * 8;
    __shared__ float red[8];

    uint4 u = *(const uint4*)(ph + base);
    __half2 h0 = *(__half2*)&u.x, h1 = *(__half2*)&u.y;
    __half2 h2 = *(__half2*)&u.z, h3 = *(__half2*)&u.w;
    float2 f0 = __half22float2(h0), f1 = __half22float2(h1);
    float2 f2 = __half22float2(h2), f3 = __half22float2(h3);
    float v[8] = {f0.x, f0.y, f1.x, f1.y, f2.x, f2.y, f3.x, f3.y};

    float mx = -3.4e38f;
#pragma unroll
    for (int i = 0; i < 8; i++) mx = fmaxf(mx, v[i]);
#pragma unroll
    for (int o = 16; o; o >>= 1) mx = fmaxf(mx, __shfl_xor_sync(0xffffffffu, mx, o));
    if ((t & 31) == 0) red[t >> 5] = mx;
    __syncthreads();
    mx = red[0];
#pragma unroll
    for (int i = 1; i < 8; i++) mx = fmaxf(mx, red[i]);

    float s = 0.f;
#pragma unroll
    for (int i = 0; i < 8; i++) { v[i] = __expf(v[i] - mx); s += v[i]; }
#pragma unroll
    for (int o = 16; o; o >>= 1) s += __shfl_xor_sync(0xffffffffu, s, o);
    __syncthreads();
    if ((t & 31) == 0) red[t >> 5] = s;
    __syncthreads();
    s = 0.f;
#pragma unroll
    for (int i = 0; i < 8; i++) s += red[i];

    const float inv = 1.0f / s;
#pragma unroll
    for (int i = 0; i < 8; i++) v[i] *= inv;

    float* p32 = S32 + (size_t)blockIdx.x * LSEQ + base;
    float4 oa = {v[0], v[1], v[2], v[3]};
    float4 ob = {v[4], v[5], v[6], v[7]};
    *(float4*)p32 = oa;
    *(float4*)(p32 + 4) = ob;

    __half2 o0 = __floats2half2_rn(v[0], v[1]);
    __half2 o1 = __floats2half2_rn(v[2], v[3]);
    __half2 o2 = __floats2half2_rn(v[4], v[5]);
    __half2 o3 = __floats2half2_rn(v[6], v[7]);
    uint4 ou = { *(uint32_t*)&o0, *(uint32_t*)&o1, *(uint32_t*)&o2, *(uint32_t*)&o3 };
    *(uint4*)(ph + base) = ou;
}

// ---------------------------------------------------------------------------
__global__ void __launch_bounds__(256)
ln_k(const float* __restrict__ X, const float* __restrict__ gam,
     const float* __restrict__ bet, float* __restrict__ Y, __half* __restrict__ Yh)
{
    const float* x = X + (size_t)blockIdx.x * HIDD;
    float*       y = Y + (size_t)blockIdx.x * HIDD;
    const int t = threadIdx.x;
    __shared__ float red[8];

    float v[4];
    float s = 0.f;
#pragma unroll
    for (int i = 0; i < 4; i++) { v[i] = x[t + 256 * i]; s += v[i]; }
#pragma unroll
    for (int o = 16; o; o >>= 1) s += __shfl_xor_sync(0xffffffffu, s, o);
    if ((t & 31) == 0) red[t >> 5] = s;
    __syncthreads();
    s = 0.f;
#pragma unroll
    for (int i = 0; i < 8; i++) s += red[i];
    const float mean = s * (1.0f / HIDD);

    float vs = 0.f;
#pragma unroll
    for (int i = 0; i < 4; i++) { float d = v[i] - mean; vs += d * d; }
#pragma unroll
    for (int o = 16; o; o >>= 1) vs += __shfl_xor_sync(0xffffffffu, vs, o);
    __syncthreads();
    if ((t & 31) == 0) red[t >> 5] = vs;
    __syncthreads();
    vs = 0.f;
#pragma unroll
    for (int i = 0; i < 8; i++) vs += red[i];
    const float inv = rsqrtf(vs * (1.0f / HIDD) + 1e-5f);

#pragma unroll
    for (int i = 0; i < 4; i++) {
        int c = t + 256 * i;
        float o = (v[i] - mean) * inv * gam[c] + bet[c];
        y[c] = o;
        if (Yh) Yh[(size_t)blockIdx.x * HIDD + c] = __float2half_rn(o);
    }
}

// ---------------------------------------------------------------------------
// Dense NT=128: 4 stages * (5120 + 32*136) halves * 2B = 75776 (>= staging 67584)
#define SMEM_DN 75776
// Scores NT=256 BT=1: staging 128*260*4 = 133120
#define SMEM_S  133120
// PV NT=64: 3 stages * (5120 + 32*72) * 2 = 44544; + 256 floats stats = 45568
#define SMEM_P  45568

extern "C" void kernel_launch(void* const* d_in, const int* in_sizes, int n_in,
                              void* d_out, int out_size)
{
    const float* tgt    = (const float*)d_in[0];
    const float* enc    = (const float*)d_in[1];
    const int*   tmask  = (const int*)  d_in[2];
    const int*   smask  = (const int*)  d_in[3];
    const float* sa_wq  = (const float*)d_in[4],  *sa_bq = (const float*)d_in[5];
    const float* sa_wk  = (const float*)d_in[6],  *sa_bk = (const float*)d_in[7];
    const float* sa_wv  = (const float*)d_in[8],  *sa_bv = (const float*)d_in[9];
    const float* sa_wo  = (const float*)d_in[10], *sa_bo = (const float*)d_in[11];
    const float* ea_wq  = (const float*)d_in[12], *ea_bq = (const float*)d_in[13];
    const float* ea_wk  = (const float*)d_in[14], *ea_bk = (const float*)d_in[15];
    const float* ea_wv  = (const float*)d_in[16], *ea_bv = (const float*)d_in[17];
    const float* ea_wo  = (const float*)d_in[18], *ea_bo = (const float*)d_in[19];
    const float* ffn_w1 = (const float*)d_in[20], *ffn_b1 = (const float*)d_in[21];
    const float* ffn_w2 = (const float*)d_in[22], *ffn_b2 = (const float*)d_in[23];
    const float* ln1_g  = (const float*)d_in[24], *ln1_b = (const float*)d_in[25];
    const float* ln2_g  = (const float*)d_in[26], *ln2_b = (const float*)d_in[27];
    const float* ln3_g  = (const float*)d_in[28], *ln3_b = (const float*)d_in[29];

    float* out     = (float*)d_out;
    float* att_out = out + (size_t)BC * LSEQ * HIDD;

    __half *qh, *kh, *vh, *aoh, *hh, *ffnh, *wth, *tgth, *ench, *sch;
    float *h, *mr, *li;
    cudaGetSymbolAddress((void**)&qh,   g_qh);
    cudaGetSymbolAddress((void**)&kh,   g_kh);
    cudaGetSymbolAddress((void**)&vh,   g_vh);
    cudaGetSymbolAddress((void**)&aoh,  g_aoh);
    cudaGetSymbolAddress((void**)&hh,   g_hh);
    cudaGetSymbolAddress((void**)&ffnh, g_ffnh);
    cudaGetSymbolAddress((void**)&wth,  g_wth);
    cudaGetSymbolAddress((void**)&tgth, g_tgth);
    cudaGetSymbolAddress((void**)&ench, g_ench);
    cudaGetSymbolAddress((void**)&sch,  g_sch);
    cudaGetSymbolAddress((void**)&h,    g_h);
    cudaGetSymbolAddress((void**)&mr,   g_mr);
    cudaGetSymbolAddress((void**)&li,   g_li);

    const size_t M1 = 1024 * 1024;

    cudaFuncSetAttribute(tc_gemm<7,128,0,2,4>, cudaFuncAttributeMaxDynamicSharedMemorySize, SMEM_DN);
    cudaFuncSetAttribute(tc_gemm<8,128,0,2,4>, cudaFuncAttributeMaxDynamicSharedMemorySize, SMEM_DN);
    cudaFuncSetAttribute(tc_gemm<1,128,0,2,4>, cudaFuncAttributeMaxDynamicSharedMemorySize, SMEM_DN);
    cudaFuncSetAttribute(tc_gemm<2,128,0,2,4>, cudaFuncAttributeMaxDynamicSharedMemorySize, SMEM_DN);
    cudaFuncSetAttribute(tc_gemm<3,128,0,2,4>, cudaFuncAttributeMaxDynamicSharedMemorySize, SMEM_DN);
    cudaFuncSetAttribute(tc_gemm<5,256,1,1,3>, cudaFuncAttributeMaxDynamicSharedMemorySize, SMEM_S);
    cudaFuncSetAttribute(tc_gemm<6,64,0,2,3>,  cudaFuncAttributeMaxDynamicSharedMemorySize, SMEM_P);
    cudaFuncSetAttribute(tc_gemm<9,64,0,2,3>,  cudaFuncAttributeMaxDynamicSharedMemorySize, SMEM_P);

    cvt_k<<<24576, 256>>>(
        (const float4*)sa_wq, (const float4*)sa_wk, (const float4*)sa_wv, (const float4*)sa_wo,
        (const float4*)ea_wq, (const float4*)ea_wk, (const float4*)ea_wv, (const float4*)ea_wo,
        (const float4*)ffn_w1, (const float4*)ffn_w2, (const float4*)tgt, (const float4*)enc,
        wth, tgth, ench);

    __half* w_saq = wth + 0 * M1; __half* w_sao = wth + 3 * M1;
    __half* w_eaq = wth + 4 * M1; __half* w_eak = wth + 5 * M1; __half* w_eao = wth + 7 * M1;
    __half* w_f1  = wth + 8 * M1; __half* w_f2  = wth + 12 * M1;

    const dim3 gqkv(24, 32);
    const dim3 gkv (16, 32);
    const dim3 gp  (8, 32);
    const dim3 gf1 (32, 32);
    const dim3 gsc (8, 16, BC * NH);
    const dim3 gpv (1, 16, BC * NH);
    const long long ABq = (long long)LSEQ * HD;
    const long long ABs = (long long)LSEQ * LSEQ;

    // ---- self-attention: scores -> stats -> PV(exp transform) ----
    tc_gemm<7,128,0,2,4><<<gqkv, 256, SMEM_DN>>>(tgth, w_saq, sa_bq, sa_bk, sa_bv, nullptr, nullptr,
                                                 qh, kh, vh, 1024, 1024, 1024, 1024, 0, 0);
    tc_gemm<5,256,1,1,3><<<gsc, 256, SMEM_S>>>(qh, kh, nullptr, nullptr, nullptr, nullptr, tmask,
                                               sch, nullptr, nullptr, 64, 64, 64, 2048, ABq, ABq);
    stats_k<<<NROWS_ATT, 256>>>(sch, mr, li);
    tc_gemm<9,64,0,2,3><<<gpv, 256, SMEM_P>>>(sch, vh, mr, li, nullptr, nullptr, nullptr,
                                              aoh, nullptr, nullptr, 2048, 2048, 64, 64, ABs, ABq);
    tc_gemm<3,128,0,2,4><<<gp, 256, SMEM_DN>>>(aoh, w_sao, sa_bo, nullptr, nullptr, tgt, nullptr,
                                               h, nullptr, nullptr, 1024, 1024, 1024, 1024, 0, 0);
    ln_k<<<MROWS, 256>>>(h, ln1_g, ln1_b, h, hh);

    // ---- cross-attention: scores -> softmax(fp32 out + fp16) -> PV ----
    tc_gemm<1,128,0,2,4><<<gp, 256, SMEM_DN>>>(hh, w_eaq, ea_bq, nullptr, nullptr, nullptr, nullptr,
                                               qh, nullptr, nullptr, 1024, 1024, 1024, 1024, 0, 0);
    tc_gemm<8,128,0,2,4><<<gkv, 256, SMEM_DN>>>(ench, w_eak, ea_bk, ea_bv, nullptr, nullptr, nullptr,
                                                kh, vh, nullptr, 1024, 1024, 1024, 1024, 0, 0);
    tc_gemm<5,256,1,1,3><<<gsc, 256, SMEM_S>>>(qh, kh, nullptr, nullptr, nullptr, nullptr, smask,
                                               sch, nullptr, nullptr, 64, 64, 64, 2048, ABq, ABq);
    softmax_hk<<<NROWS_ATT, 256>>>(sch, att_out);
    tc_gemm<6,64,0,2,3><<<gpv, 256, SMEM_P>>>(sch, vh, nullptr, nullptr, nullptr, nullptr, nullptr,
                                              aoh, nullptr, nullptr, 2048, 2048, 64, 64, ABs, ABq);
    tc_gemm<3,128,0,2,4><<<gp, 256, SMEM_DN>>>(aoh, w_eao, ea_bo, nullptr, nullptr, h, nullptr,
                                               h, nullptr, nullptr, 1024, 1024, 1024, 1024, 0, 0);
    ln_k<<<MROWS, 256>>>(h, ln2_g, ln2_b, h, hh);

    // ---- FFN ----
    tc_gemm<2,128,0,2,4><<<gf1, 256, SMEM_DN>>>(hh, w_f1, ffn_b1, nullptr, nullptr, nullptr, nullptr,
                                                ffnh, nullptr, nullptr, 1024, 1024, 4096, 4096, 0, 0);
    tc_gemm<3,128,0,2,4><<<gp, 256, SMEM_DN>>>(ffnh, w_f2, ffn_b2, nullptr, nullptr, h, nullptr,
                                               h, nullptr, nullptr, 4096, 4096, 1024, 1024, 0, 0);
    ln_k<<<MROWS, 256>>>(h, ln3_g, ln3_b, out, nullptr);
}